// round 5
// baseline (speedup 1.0000x reference)
#include <cuda_runtime.h>
#include <cuda_bf16.h>
#include <math.h>
#include <stdint.h>

// Problem constants (fixed by the reference)
#define NN   50000
#define EE   400000
#define FIN  128
#define NH   3
#define DD   64
#define HD   192   // NH*DD
#define GG   64
#define PP   64

// ---------------- scratch (device globals; no allocation) ----------------
__device__ float g_fs[(size_t)NN * HD];
__device__ float g_fd[(size_t)NN * HD];
__device__ float g_h [(size_t)NN * HD];
__device__ float g_gsum[GG * DD];
__device__ float g_gcnt[GG];
// CSR by dst (built once per launch; dst does not change across layers)
__device__ int g_deg[NN];
__device__ int g_off[NN + 1];
__device__ int g_cur[NN];
__device__ int g_esrc[EE];

static inline int cdiv(int a, int b) { return (a + b - 1) / b; }

// ---------------- launch-wide init ----------------
__global__ void k_init() {
    int idx = blockIdx.x * blockDim.x + threadIdx.x;
    if (idx < NN) g_deg[idx] = 0;
    if (idx < GG * DD) g_gsum[idx] = 0.0f;
    if (idx < GG) g_gcnt[idx] = 0.0f;
}

__global__ void k_hist(const int* __restrict__ dst) {
    int e = blockIdx.x * blockDim.x + threadIdx.x;
    if (e < EE) atomicAdd(&g_deg[dst[e]], 1);
}

// single-block exclusive scan of g_deg -> g_off (and g_cur copy)
__global__ void k_scan() {
    __shared__ int s_warp[32];
    int tid = threadIdx.x;
    int lane = tid & 31, wid = tid >> 5;
    int running = 0;
    for (int base = 0; base < NN; base += 1024) {
        int i = base + tid;
        int v = (i < NN) ? g_deg[i] : 0;
        int x = v;
#pragma unroll
        for (int o = 1; o < 32; o <<= 1) {
            int y = __shfl_up_sync(0xFFFFFFFFu, x, o);
            if (lane >= o) x += y;
        }
        if (lane == 31) s_warp[wid] = x;
        __syncthreads();
        if (wid == 0) {
            int w = s_warp[lane];
#pragma unroll
            for (int o = 1; o < 32; o <<= 1) {
                int y = __shfl_up_sync(0xFFFFFFFFu, w, o);
                if (lane >= o) w += y;
            }
            s_warp[lane] = w;
        }
        __syncthreads();
        int excl = running + x - v + (wid > 0 ? s_warp[wid - 1] : 0);
        if (i < NN) { g_off[i] = excl; g_cur[i] = excl; }
        int total = s_warp[31];
        __syncthreads();
        running += total;
    }
    if (tid == 0) g_off[NN] = running;
}

__global__ void k_scatter(const int* __restrict__ src, const int* __restrict__ dst) {
    int e = blockIdx.x * blockDim.x + threadIdx.x;
    if (e >= EE) return;
    int t = dst[e];
    int pos = atomicAdd(&g_cur[t], 1);
    g_esrc[pos] = src[e];
}

// ---------------- cp.async helpers ----------------
__device__ __forceinline__ void cp16(uint32_t dst_smem, const void* src, bool valid) {
    int sz = valid ? 16 : 0;
    asm volatile("cp.async.cg.shared.global [%0], [%1], 16, %2;"
                 :: "r"(dst_smem), "l"(src), "r"(sz));
}
__device__ __forceinline__ void cp_commit() {
    asm volatile("cp.async.commit_group;");
}
template <int Nres>
__device__ __forceinline__ void cp_wait() {
    asm volatile("cp.async.wait_group %0;" :: "n"(Nres));
}

// ---------------- tf32 tensor-core dual GEMM (double-buffered cp.async) ----------
// C0 = A @ B0, C1 = A @ B1 (blockIdx.z picks), BM=128, BN=64, BK=32, 256 thr.
// A tile stored [m][k] stride 36 (bank-conflict-free frags), B tile [k][n] stride 72.
// tf32 via HW truncation of fp32 operands.
#define TBM 128
#define TBN 64
#define TBK 32
#define ASTR 36
#define BSTR 72
#define ASZ (TBM * ASTR)   // 4608 floats
#define BSZ (TBK * BSTR)   // 2304 floats
#define GEMM_SMEM ((2 * (ASZ + BSZ)) * 4)

__global__ void k_gemm_dual(const float* __restrict__ A,
                            const float* __restrict__ B0, const float* __restrict__ B1,
                            float* __restrict__ C0, float* __restrict__ C1,
                            int M, int K, int Nc) {
    extern __shared__ float smem[];
    float* As = smem;                 // [2][ASZ]
    float* Bs = smem + 2 * ASZ;       // [2][BSZ]
    const float* B = blockIdx.z ? B1 : B0;
    float* C = blockIdx.z ? C1 : C0;

    int tid = threadIdx.x;
    int warp = tid >> 5, lane = tid & 31;
    int warp_m = warp & 3, warp_n = warp >> 2;   // 4 x 2 warps, 32x32 tiles
    int row0 = blockIdx.y * TBM;
    int col0 = blockIdx.x * TBN;
    int gid = lane >> 2, tig = lane & 3;

    uint32_t s_as = (uint32_t)__cvta_generic_to_shared(As);
    uint32_t s_bs = (uint32_t)__cvta_generic_to_shared(Bs);

    int nIter = K / TBK;

    // --- load tile 'it' into buffer buf ---
    auto load_tile = [&](int it, int buf) {
        int k0 = it * TBK;
        uint32_t abase = s_as + (uint32_t)buf * ASZ * 4;
        uint32_t bbase = s_bs + (uint32_t)buf * BSZ * 4;
#pragma unroll
        for (int i = 0; i < 4; i++) {
            int c = tid + i * 256;             // 1024 chunks of 16B
            int r = c >> 3, off = (c & 7) * 4;
            bool v = (row0 + r) < M;
            cp16(abase + (uint32_t)(r * ASTR + off) * 4,
                 A + (size_t)(row0 + r) * K + k0 + off, v);
        }
#pragma unroll
        for (int i = 0; i < 2; i++) {
            int c = tid + i * 256;             // 512 chunks
            int r = c >> 4, off = (c & 15) * 4;
            cp16(bbase + (uint32_t)(r * BSTR + off) * 4,
                 B + (size_t)(k0 + r) * Nc + col0 + off, true);
        }
        cp_commit();
    };

    float acc[2][4][4] = {};

    load_tile(0, 0);
    for (int it = 0; it < nIter; it++) {
        int buf = it & 1;
        if (it + 1 < nIter) { load_tile(it + 1, buf ^ 1); cp_wait<1>(); }
        else                { cp_wait<0>(); }
        __syncthreads();

        const float* Ab = As + buf * ASZ;
        const float* Bb = Bs + buf * BSZ;
#pragma unroll
        for (int ks = 0; ks < TBK / 8; ks++) {
            int kb = ks * 8;
            uint32_t a[2][4], b[4][2];
#pragma unroll
            for (int mt = 0; mt < 2; mt++) {
                int r = warp_m * 32 + mt * 16 + gid;
                const float* p0 = Ab + (size_t)r * ASTR + kb + tig;
                const float* p1 = Ab + (size_t)(r + 8) * ASTR + kb + tig;
                a[mt][0] = __float_as_uint(p0[0]);
                a[mt][1] = __float_as_uint(p1[0]);
                a[mt][2] = __float_as_uint(p0[4]);
                a[mt][3] = __float_as_uint(p1[4]);
            }
#pragma unroll
            for (int nt = 0; nt < 4; nt++) {
                int cn = warp_n * 32 + nt * 8 + gid;
                b[nt][0] = __float_as_uint(Bb[(size_t)(kb + tig) * BSTR + cn]);
                b[nt][1] = __float_as_uint(Bb[(size_t)(kb + tig + 4) * BSTR + cn]);
            }
#pragma unroll
            for (int mt = 0; mt < 2; mt++)
#pragma unroll
                for (int nt = 0; nt < 4; nt++)
                    asm volatile(
                        "mma.sync.aligned.m16n8k8.row.col.f32.tf32.tf32.f32 "
                        "{%0,%1,%2,%3}, {%4,%5,%6,%7}, {%8,%9}, {%0,%1,%2,%3};"
                        : "+f"(acc[mt][nt][0]), "+f"(acc[mt][nt][1]),
                          "+f"(acc[mt][nt][2]), "+f"(acc[mt][nt][3])
                        : "r"(a[mt][0]), "r"(a[mt][1]), "r"(a[mt][2]), "r"(a[mt][3]),
                          "r"(b[nt][0]), "r"(b[nt][1]));
        }
        __syncthreads();
    }

    // epilogue
#pragma unroll
    for (int mt = 0; mt < 2; mt++) {
        int r = row0 + warp_m * 32 + mt * 16 + gid;
#pragma unroll
        for (int nt = 0; nt < 4; nt++) {
            int cn = col0 + warp_n * 32 + nt * 8 + tig * 2;
            if (r < M)
                *(float2*)(C + (size_t)r * Nc + cn) = make_float2(acc[mt][nt][0], acc[mt][nt][1]);
            if (r + 8 < M)
                *(float2*)(C + (size_t)(r + 8) * Nc + cn) = make_float2(acc[mt][nt][2], acc[mt][nt][3]);
        }
    }
}

// ---------------- fused GATv2 edge softmax + aggregation (3 heads/warp) ----------
// One warp per dst node; lane holds dims {2*lane, 2*lane+1} of each head.
// mode 0: write out[n,HD]; mode 1: head-mean + graph pooling (atomic) fused.
__global__ void k_gat(const float* __restrict__ attn, const float* __restrict__ bias,
                      float* __restrict__ out, const int* __restrict__ gid, int mode) {
    int n = (blockIdx.x * blockDim.x + threadIdx.x) >> 5;
    int lane = threadIdx.x & 31;
    if (n >= NN) return;
    int base = lane * 2;

    const float* pfd = g_fd + (size_t)n * HD + base;
    float2 fd0 = *(const float2*)(pfd);
    float2 fd1 = *(const float2*)(pfd + DD);
    float2 fd2 = *(const float2*)(pfd + 2 * DD);
    float2 a0 = __ldg((const float2*)(attn + base));
    float2 a1 = __ldg((const float2*)(attn + DD + base));
    float2 a2 = __ldg((const float2*)(attn + 2 * DD + base));

    float m0 = -INFINITY, m1 = -INFINITY, m2 = -INFINITY;
    float d0 = 0.f, d1 = 0.f, d2 = 0.f;
    float x0 = 0.f, y0 = 0.f, x1 = 0.f, y1 = 0.f, x2 = 0.f, y2 = 0.f;

    int beg = g_off[n], end = g_off[n + 1];
    for (int i = beg; i < end; i++) {
        int s = __ldg(&g_esrc[i]);
        const float* pf = g_fs + (size_t)s * HD + base;
        float2 f0 = *(const float2*)(pf);
        float2 f1 = *(const float2*)(pf + DD);
        float2 f2 = *(const float2*)(pf + 2 * DD);

        float v, p0, p1, p2;
        v = f0.x + fd0.x; v = v > 0.f ? v : 0.2f * v; p0 = a0.x * v;
        v = f0.y + fd0.y; v = v > 0.f ? v : 0.2f * v; p0 = fmaf(a0.y, v, p0);
        v = f1.x + fd1.x; v = v > 0.f ? v : 0.2f * v; p1 = a1.x * v;
        v = f1.y + fd1.y; v = v > 0.f ? v : 0.2f * v; p1 = fmaf(a1.y, v, p1);
        v = f2.x + fd2.x; v = v > 0.f ? v : 0.2f * v; p2 = a2.x * v;
        v = f2.y + fd2.y; v = v > 0.f ? v : 0.2f * v; p2 = fmaf(a2.y, v, p2);
#pragma unroll
        for (int o = 16; o; o >>= 1) {
            p0 += __shfl_xor_sync(0xFFFFFFFFu, p0, o);
            p1 += __shfl_xor_sync(0xFFFFFFFFu, p1, o);
            p2 += __shfl_xor_sync(0xFFFFFFFFu, p2, o);
        }
        // online softmax (warp-uniform branches)
        if (p0 <= m0) { float e = expf(p0 - m0); d0 += e; x0 = fmaf(e, f0.x, x0); y0 = fmaf(e, f0.y, y0); }
        else { float sc = expf(m0 - p0); d0 = fmaf(d0, sc, 1.f); x0 = fmaf(x0, sc, f0.x); y0 = fmaf(y0, sc, f0.y); m0 = p0; }
        if (p1 <= m1) { float e = expf(p1 - m1); d1 += e; x1 = fmaf(e, f1.x, x1); y1 = fmaf(e, f1.y, y1); }
        else { float sc = expf(m1 - p1); d1 = fmaf(d1, sc, 1.f); x1 = fmaf(x1, sc, f1.x); y1 = fmaf(y1, sc, f1.y); m1 = p1; }
        if (p2 <= m2) { float e = expf(p2 - m2); d2 += e; x2 = fmaf(e, f2.x, x2); y2 = fmaf(e, f2.y, y2); }
        else { float sc = expf(m2 - p2); d2 = fmaf(d2, sc, 1.f); x2 = fmaf(x2, sc, f2.x); y2 = fmaf(y2, sc, f2.y); m2 = p2; }
    }

    float i0 = 1.f / fmaxf(d0, 1e-9f);
    float i1 = 1.f / fmaxf(d1, 1e-9f);
    float i2 = 1.f / fmaxf(d2, 1e-9f);
    float2 b0 = __ldg((const float2*)(bias + base));
    float2 b1 = __ldg((const float2*)(bias + DD + base));
    float2 b2 = __ldg((const float2*)(bias + 2 * DD + base));
    float o0x = fmaf(x0, i0, b0.x), o0y = fmaf(y0, i0, b0.y);
    float o1x = fmaf(x1, i1, b1.x), o1y = fmaf(y1, i1, b1.y);
    float o2x = fmaf(x2, i2, b2.x), o2y = fmaf(y2, i2, b2.y);

    if (mode == 0) {
        float* po = out + (size_t)n * HD + base;
        *(float2*)(po)           = make_float2(o0x, o0y);
        *(float2*)(po + DD)      = make_float2(o1x, o1y);
        *(float2*)(po + 2 * DD)  = make_float2(o2x, o2y);
    } else {
        float mx = (o0x + o1x + o2x) * (1.0f / 3.0f);
        float my = (o0y + o1y + o2y) * (1.0f / 3.0f);
        int g = __ldg(&gid[n]);
        atomicAdd(&g_gsum[g * DD + base], mx);
        atomicAdd(&g_gsum[g * DD + base + 1], my);
        if (lane == 0) atomicAdd(&g_gcnt[g], 1.0f);
    }
}

// ---------------- pattern branch + classifier head ----------------
__global__ void k_head(const float* __restrict__ p1, const float* __restrict__ p2,
                       const float* __restrict__ p3,
                       const float* __restrict__ Wex, const float* __restrict__ bex,
                       const float* __restrict__ Wpat, const float* __restrict__ bpat,
                       const float* __restrict__ Wc1, const float* __restrict__ bc1,
                       const float* __restrict__ Wc2, const float* __restrict__ bc2,
                       const float* __restrict__ Wc3, const float* __restrict__ bc3,
                       float* __restrict__ out) {
    int g = blockIdx.x;
    int tid = threadIdx.x;
    __shared__ float s_ex[96];
    __shared__ float s_x[128];
    __shared__ float s_c1[64];
    __shared__ float s_c2[32];

    if (tid < 96) {
        int part = tid / 32, j = tid % 32;
        const float* p = (part == 0) ? p1 : (part == 1) ? p2 : p3;
        float acc = bex[j];
        for (int k = 0; k < PP; k++) acc = fmaf(p[g * PP + k], Wex[k * 32 + j], acc);
        s_ex[tid] = acc;
    }
    __syncthreads();

    if (tid < 64) {
        float cnt = fmaxf(g_gcnt[g], 1.0f);
        s_x[tid] = g_gsum[g * DD + tid] / cnt;
    } else {
        int j = tid - 64;
        float acc = bpat[j];
        for (int k = 0; k < 96; k++) acc = fmaf(s_ex[k], Wpat[k * PP + j], acc);
        s_x[tid] = acc > 0.f ? acc : 0.01f * acc;
    }
    __syncthreads();

    if (tid < 64) {
        float acc = bc1[tid];
        for (int k = 0; k < 128; k++) acc = fmaf(s_x[k], Wc1[k * 64 + tid], acc);
        s_c1[tid] = acc > 0.f ? acc : 0.01f * acc;
    }
    __syncthreads();

    if (tid < 32) {
        float acc = bc2[tid];
        for (int k = 0; k < 64; k++) acc = fmaf(s_c1[k], Wc2[k * 32 + tid], acc);
        s_c2[tid] = acc > 0.f ? acc : 0.01f * acc;
    }
    __syncthreads();

    if (tid < 2) {
        float acc = bc3[tid];
        for (int k = 0; k < 32; k++) acc = fmaf(s_c2[k], Wc3[k * 2 + tid], acc);
        out[g * 2 + tid] = acc;
    }
}

// ---------------- driver ----------------
extern "C" void kernel_launch(void* const* d_in, const int* in_sizes, int n_in,
                              void* d_out, int out_size) {
    const float* inputs = (const float*)d_in[0];
    const int*   src    = (const int*)d_in[1];
    const int*   dst    = (const int*)d_in[2];
    const int*   gid    = (const int*)d_in[3];
    const float* p1     = (const float*)d_in[4];
    const float* p2     = (const float*)d_in[5];
    const float* p3     = (const float*)d_in[6];
    const float* W1s = (const float*)d_in[7],  *W1d = (const float*)d_in[8];
    const float* a1  = (const float*)d_in[9],  *b1  = (const float*)d_in[10];
    const float* W2s = (const float*)d_in[11], *W2d = (const float*)d_in[12];
    const float* a2  = (const float*)d_in[13], *b2  = (const float*)d_in[14];
    const float* W3s = (const float*)d_in[15], *W3d = (const float*)d_in[16];
    const float* a3  = (const float*)d_in[17], *b3  = (const float*)d_in[18];
    const float* Wex = (const float*)d_in[19], *bex = (const float*)d_in[20];
    const float* Wpat= (const float*)d_in[21], *bpat= (const float*)d_in[22];
    const float* Wc1 = (const float*)d_in[23], *bc1 = (const float*)d_in[24];
    const float* Wc2 = (const float*)d_in[25], *bc2 = (const float*)d_in[26];
    const float* Wc3 = (const float*)d_in[27], *bc3 = (const float*)d_in[28];

    float *p_fs, *p_fd, *p_h;
    cudaGetSymbolAddress((void**)&p_fs, g_fs);
    cudaGetSymbolAddress((void**)&p_fd, g_fd);
    cudaGetSymbolAddress((void**)&p_h,  g_h);

    static int smem_set = 0;
    if (!smem_set) {
        cudaFuncSetAttribute(k_gemm_dual, cudaFuncAttributeMaxDynamicSharedMemorySize,
                             GEMM_SMEM);
        smem_set = 1;
    }

    const int T = 256;
    // CSR build (dst is the same for all layers)
    k_init<<<cdiv(NN, T), T>>>();
    k_hist<<<cdiv(EE, T), T>>>(dst);
    k_scan<<<1, 1024>>>();
    k_scatter<<<cdiv(EE, T), T>>>(src, dst);

    dim3 ggrid(HD / TBN, cdiv(NN, TBM), 2);
    int gat_grid = cdiv(NN * 32, T);

    k_gemm_dual<<<ggrid, 256, GEMM_SMEM>>>(inputs, W1s, W1d, p_fs, p_fd, NN, FIN, HD);
    k_gat<<<gat_grid, T>>>(a1, b1, p_h, gid, 0);
    k_gemm_dual<<<ggrid, 256, GEMM_SMEM>>>(p_h, W2s, W2d, p_fs, p_fd, NN, HD, HD);
    k_gat<<<gat_grid, T>>>(a2, b2, p_h, gid, 0);
    k_gemm_dual<<<ggrid, 256, GEMM_SMEM>>>(p_h, W3s, W3d, p_fs, p_fd, NN, HD, HD);
    k_gat<<<gat_grid, T>>>(a3, b3, nullptr, gid, 1);

    k_head<<<GG, 128>>>(p1, p2, p3, Wex, bex, Wpat, bpat,
                        Wc1, bc1, Wc2, bc2, Wc3, bc3, (float*)d_out);
}

// round 6
// speedup vs baseline: 1.3892x; 1.3892x over previous
#include <cuda_runtime.h>
#include <cuda_bf16.h>
#include <math.h>
#include <stdint.h>

// Problem constants (fixed by the reference)
#define NN   50000
#define EE   400000
#define FIN  128
#define NH   3
#define DD   64
#define HD   192   // NH*DD
#define GG   64
#define PP   64

// ---------------- scratch (device globals; no allocation) ----------------
__device__ float g_fs[(size_t)NN * HD];
__device__ float g_fd[(size_t)NN * HD];
__device__ __nv_bfloat16 g_xb[(size_t)NN * HD];   // bf16 activations (GEMM A input)
__device__ __nv_bfloat16 g_wT[6 * HD * HD];       // 6 transposed bf16 weight mats [N][K]
__device__ float g_gsum[GG * DD];
__device__ float g_gcnt[GG];
// CSR by dst (built once per launch; dst does not change across layers)
__device__ int g_deg[NN];
__device__ int g_off[NN + 1];
__device__ int g_cur[NN];
__device__ int g_esrc[EE];

static inline int cdiv(int a, int b) { return (a + b - 1) / b; }

// ---------------- conversions ----------------
// inputs fp32 [NN][FIN] -> g_xb bf16 compact [NN][FIN]
__global__ void k_cvt_in(const float* __restrict__ in) {
    int idx = blockIdx.x * blockDim.x + threadIdx.x;   // float4 index
    if (idx >= NN * FIN / 4) return;
    float4 v = ((const float4*)in)[idx];
    __nv_bfloat162 lo = __floats2bfloat162_rn(v.x, v.y);
    __nv_bfloat162 hi = __floats2bfloat162_rn(v.z, v.w);
    uint32_t* o = (uint32_t*)g_xb;
    o[idx * 2 + 0] = *(uint32_t*)&lo;
    o[idx * 2 + 1] = *(uint32_t*)&hi;
}

// weights fp32 [K][N] -> g_wT bf16 [N][K], slot z (z<2: K=FIN else K=HD)
__global__ void k_cvt_w(const float* __restrict__ w0, const float* __restrict__ w1,
                        const float* __restrict__ w2, const float* __restrict__ w3,
                        const float* __restrict__ w4, const float* __restrict__ w5) {
    int z = blockIdx.z;
    const float* in = (z == 0) ? w0 : (z == 1) ? w1 : (z == 2) ? w2
                    : (z == 3) ? w3 : (z == 4) ? w4 : w5;
    int K = (z < 2) ? FIN : HD;
    int idx = blockIdx.x * blockDim.x + threadIdx.x;
    if (idx >= K * HD) return;
    int n = idx / K, k = idx - n * K;
    g_wT[(size_t)z * HD * HD + (size_t)n * K + k] = __float2bfloat16(in[(size_t)k * HD + n]);
}

// ---------------- launch-wide init ----------------
__global__ void k_init() {
    int idx = blockIdx.x * blockDim.x + threadIdx.x;
    if (idx < NN) g_deg[idx] = 0;
    if (idx < GG * DD) g_gsum[idx] = 0.0f;
    if (idx < GG) g_gcnt[idx] = 0.0f;
}

__global__ void k_hist(const int* __restrict__ dst) {
    int e = blockIdx.x * blockDim.x + threadIdx.x;
    if (e < EE) atomicAdd(&g_deg[dst[e]], 1);
}

// single-block exclusive scan of g_deg -> g_off (and g_cur copy)
__global__ void k_scan() {
    __shared__ int s_warp[32];
    int tid = threadIdx.x;
    int lane = tid & 31, wid = tid >> 5;
    int running = 0;
    for (int base = 0; base < NN; base += 1024) {
        int i = base + tid;
        int v = (i < NN) ? g_deg[i] : 0;
        int x = v;
#pragma unroll
        for (int o = 1; o < 32; o <<= 1) {
            int y = __shfl_up_sync(0xFFFFFFFFu, x, o);
            if (lane >= o) x += y;
        }
        if (lane == 31) s_warp[wid] = x;
        __syncthreads();
        if (wid == 0) {
            int w = s_warp[lane];
#pragma unroll
            for (int o = 1; o < 32; o <<= 1) {
                int y = __shfl_up_sync(0xFFFFFFFFu, w, o);
                if (lane >= o) w += y;
            }
            s_warp[lane] = w;
        }
        __syncthreads();
        int excl = running + x - v + (wid > 0 ? s_warp[wid - 1] : 0);
        if (i < NN) { g_off[i] = excl; g_cur[i] = excl; }
        int total = s_warp[31];
        __syncthreads();
        running += total;
    }
    if (tid == 0) g_off[NN] = running;
}

__global__ void k_scatter(const int* __restrict__ src, const int* __restrict__ dst) {
    int e = blockIdx.x * blockDim.x + threadIdx.x;
    if (e >= EE) return;
    int t = dst[e];
    int pos = atomicAdd(&g_cur[t], 1);
    g_esrc[pos] = src[e];
}

// ---------------- bf16 tensor-core dual GEMM ----------------
// C = A[M,K](bf16) @ B^T  where BT is [Nc][K] bf16 (k-contiguous).
// blockIdx.z picks (BT0,C0) vs (BT1,C1). BM=128, BN=64, BK=32, 256 thr (8 warps 4x2),
// warp tile 32x32 via m16n8k16. Smem u32 rows stride 20 (conflict-free frags).
#define TBM 128
#define TBN 64
#define TBK 32
#define ASTR 20
#define BSTR 20
__global__ void k_gemm(const __nv_bfloat16* __restrict__ A,
                       const __nv_bfloat16* __restrict__ BT0,
                       const __nv_bfloat16* __restrict__ BT1,
                       float* __restrict__ C0, float* __restrict__ C1,
                       int M, int K, int Nc) {
    __shared__ uint32_t As[TBM * ASTR];   // [m][k/2] u32
    __shared__ uint32_t Bs[TBN * BSTR];   // [n][k/2] u32
    const __nv_bfloat16* BT = blockIdx.z ? BT1 : BT0;
    float* C = blockIdx.z ? C1 : C0;

    int tid = threadIdx.x;
    int warp = tid >> 5, lane = tid & 31;
    int warp_m = warp & 3, warp_n = warp >> 2;
    int row0 = blockIdx.y * TBM;
    int col0 = blockIdx.x * TBN;
    int gid = lane >> 2, tig = lane & 3;

    float acc[2][4][4] = {};

    for (int k0 = 0; k0 < K; k0 += TBK) {
        // A tile: 128 rows x 32 k = 512 uint4 chunks (8 bf16 each), 2/thread
#pragma unroll
        for (int j = 0; j < 2; j++) {
            int c = tid + j * 256;
            int r = c >> 2, q = c & 3;
            uint4 v = make_uint4(0, 0, 0, 0);
            if (row0 + r < M)
                v = *(const uint4*)(A + (size_t)(row0 + r) * K + k0 + q * 8);
            *(uint4*)&As[r * ASTR + q * 4] = v;
        }
        // B tile: 64 rows x 32 k = 256 uint4 chunks, 1/thread
        {
            int n = tid >> 2, q = tid & 3;
            uint4 v = *(const uint4*)(BT + (size_t)(col0 + n) * K + k0 + q * 8);
            *(uint4*)&Bs[n * BSTR + q * 4] = v;
        }
        __syncthreads();

#pragma unroll
        for (int ks = 0; ks < 2; ks++) {
            int off = ks * 8;
            uint32_t a[2][4], b[4][2];
#pragma unroll
            for (int mt = 0; mt < 2; mt++) {
                int r = warp_m * 32 + mt * 16 + gid;
                int base = r * ASTR + off + tig;
                a[mt][0] = As[base];
                a[mt][1] = As[base + 8 * ASTR];
                a[mt][2] = As[base + 4];
                a[mt][3] = As[base + 8 * ASTR + 4];
            }
#pragma unroll
            for (int nt = 0; nt < 4; nt++) {
                int n = warp_n * 32 + nt * 8 + gid;
                b[nt][0] = Bs[n * BSTR + off + tig];
                b[nt][1] = Bs[n * BSTR + off + tig + 4];
            }
#pragma unroll
            for (int mt = 0; mt < 2; mt++)
#pragma unroll
                for (int nt = 0; nt < 4; nt++)
                    asm volatile(
                        "mma.sync.aligned.m16n8k16.row.col.f32.bf16.bf16.f32 "
                        "{%0,%1,%2,%3}, {%4,%5,%6,%7}, {%8,%9}, {%0,%1,%2,%3};"
                        : "+f"(acc[mt][nt][0]), "+f"(acc[mt][nt][1]),
                          "+f"(acc[mt][nt][2]), "+f"(acc[mt][nt][3])
                        : "r"(a[mt][0]), "r"(a[mt][1]), "r"(a[mt][2]), "r"(a[mt][3]),
                          "r"(b[nt][0]), "r"(b[nt][1]));
        }
        __syncthreads();
    }

    // epilogue (fp32 out)
#pragma unroll
    for (int mt = 0; mt < 2; mt++) {
        int r = row0 + warp_m * 32 + mt * 16 + gid;
#pragma unroll
        for (int nt = 0; nt < 4; nt++) {
            int cn = col0 + warp_n * 32 + nt * 8 + tig * 2;
            if (r < M)
                *(float2*)(C + (size_t)r * Nc + cn) = make_float2(acc[mt][nt][0], acc[mt][nt][1]);
            if (r + 8 < M)
                *(float2*)(C + (size_t)(r + 8) * Nc + cn) = make_float2(acc[mt][nt][2], acc[mt][nt][3]);
        }
    }
}

// ---------------- fused GATv2 edge softmax + aggregation ----------------
// One warp per (dst node, head). Online softmax over in-edges (CSR order).
// Output written as bf16 (next layer's GEMM A input / pooling input).
__global__ void k_gat(const float* __restrict__ attn, const float* __restrict__ bias) {
    int w = (blockIdx.x * blockDim.x + threadIdx.x) >> 5;
    int lane = threadIdx.x & 31;
    if (w >= NN * NH) return;
    int n = w / NH, h = w - n * NH;
    int base = h * DD + lane * 2;

    float2 fd2 = *(const float2*)(g_fd + (size_t)n * HD + base);
    float2 a2  = __ldg((const float2*)(attn + base));

    float m = -INFINITY, den = 0.f, accx = 0.f, accy = 0.f;
    int beg = g_off[n], end = g_off[n + 1];
    for (int i = beg; i < end; i++) {
        int s = g_esrc[i];
        float2 fs2 = *(const float2*)(g_fs + (size_t)s * HD + base);
        float vx = fs2.x + fd2.x; vx = vx > 0.f ? vx : 0.2f * vx;
        float vy = fs2.y + fd2.y; vy = vy > 0.f ? vy : 0.2f * vy;
        float p = fmaf(a2.x, vx, a2.y * vy);
#pragma unroll
        for (int o = 16; o; o >>= 1) p += __shfl_xor_sync(0xFFFFFFFFu, p, o);
        if (p <= m) {
            float ex = expf(p - m);
            den += ex;
            accx = fmaf(ex, fs2.x, accx);
            accy = fmaf(ex, fs2.y, accy);
        } else {
            float sc = expf(m - p);   // exp(-inf)=0 handles first edge
            den = fmaf(den, sc, 1.f);
            accx = fmaf(accx, sc, fs2.x);
            accy = fmaf(accy, sc, fs2.y);
            m = p;
        }
    }
    float inv = 1.f / fmaxf(den, 1e-9f);
    float2 b2 = __ldg((const float2*)(bias + base));
    float ox = fmaf(accx, inv, b2.x);
    float oy = fmaf(accy, inv, b2.y);
    __nv_bfloat162 pk = __floats2bfloat162_rn(ox, oy);
    ((uint32_t*)g_xb)[(size_t)n * (HD / 2) + h * (DD / 2) + lane] = *(uint32_t*)&pk;
}

// layer-3: mean over heads (bf16 h) + graph pooling
__global__ void k_poolmean(const int* __restrict__ gid) {
    int idx = blockIdx.x * blockDim.x + threadIdx.x;
    if (idx >= NN * DD) return;
    int n = idx / DD, d = idx - n * DD;
    const __nv_bfloat16* p = g_xb + (size_t)n * HD;
    float v = (__bfloat162float(p[d]) + __bfloat162float(p[DD + d]) +
               __bfloat162float(p[2 * DD + d])) * (1.0f / 3.0f);
    int g = __ldg(&gid[n]);
    atomicAdd(&g_gsum[g * DD + d], v);
    if (d == 0) atomicAdd(&g_gcnt[g], 1.0f);
}

// ---------------- pattern branch + classifier head ----------------
__global__ void k_head(const float* __restrict__ p1, const float* __restrict__ p2,
                       const float* __restrict__ p3,
                       const float* __restrict__ Wex, const float* __restrict__ bex,
                       const float* __restrict__ Wpat, const float* __restrict__ bpat,
                       const float* __restrict__ Wc1, const float* __restrict__ bc1,
                       const float* __restrict__ Wc2, const float* __restrict__ bc2,
                       const float* __restrict__ Wc3, const float* __restrict__ bc3,
                       float* __restrict__ out) {
    int g = blockIdx.x;
    int tid = threadIdx.x;
    __shared__ float s_ex[96];
    __shared__ float s_x[128];
    __shared__ float s_c1[64];
    __shared__ float s_c2[32];

    if (tid < 96) {
        int part = tid / 32, j = tid % 32;
        const float* p = (part == 0) ? p1 : (part == 1) ? p2 : p3;
        float acc = bex[j];
        for (int k = 0; k < PP; k++) acc = fmaf(p[g * PP + k], Wex[k * 32 + j], acc);
        s_ex[tid] = acc;
    }
    __syncthreads();

    if (tid < 64) {
        float cnt = fmaxf(g_gcnt[g], 1.0f);
        s_x[tid] = g_gsum[g * DD + tid] / cnt;
    } else {
        int j = tid - 64;
        float acc = bpat[j];
        for (int k = 0; k < 96; k++) acc = fmaf(s_ex[k], Wpat[k * PP + j], acc);
        s_x[tid] = acc > 0.f ? acc : 0.01f * acc;
    }
    __syncthreads();

    if (tid < 64) {
        float acc = bc1[tid];
        for (int k = 0; k < 128; k++) acc = fmaf(s_x[k], Wc1[k * 64 + tid], acc);
        s_c1[tid] = acc > 0.f ? acc : 0.01f * acc;
    }
    __syncthreads();

    if (tid < 32) {
        float acc = bc2[tid];
        for (int k = 0; k < 64; k++) acc = fmaf(s_c1[k], Wc2[k * 32 + tid], acc);
        s_c2[tid] = acc > 0.f ? acc : 0.01f * acc;
    }
    __syncthreads();

    if (tid < 2) {
        float acc = bc3[tid];
        for (int k = 0; k < 32; k++) acc = fmaf(s_c2[k], Wc3[k * 2 + tid], acc);
        out[g * 2 + tid] = acc;
    }
}

// ---------------- driver ----------------
extern "C" void kernel_launch(void* const* d_in, const int* in_sizes, int n_in,
                              void* d_out, int out_size) {
    const float* inputs = (const float*)d_in[0];
    const int*   src    = (const int*)d_in[1];
    const int*   dst    = (const int*)d_in[2];
    const int*   gid    = (const int*)d_in[3];
    const float* p1     = (const float*)d_in[4];
    const float* p2     = (const float*)d_in[5];
    const float* p3     = (const float*)d_in[6];
    const float* W1s = (const float*)d_in[7],  *W1d = (const float*)d_in[8];
    const float* a1  = (const float*)d_in[9],  *b1  = (const float*)d_in[10];
    const float* W2s = (const float*)d_in[11], *W2d = (const float*)d_in[12];
    const float* a2  = (const float*)d_in[13], *b2  = (const float*)d_in[14];
    const float* W3s = (const float*)d_in[15], *W3d = (const float*)d_in[16];
    const float* a3  = (const float*)d_in[17], *b3  = (const float*)d_in[18];
    const float* Wex = (const float*)d_in[19], *bex = (const float*)d_in[20];
    const float* Wpat= (const float*)d_in[21], *bpat= (const float*)d_in[22];
    const float* Wc1 = (const float*)d_in[23], *bc1 = (const float*)d_in[24];
    const float* Wc2 = (const float*)d_in[25], *bc2 = (const float*)d_in[26];
    const float* Wc3 = (const float*)d_in[27], *bc3 = (const float*)d_in[28];

    float *p_fs, *p_fd;
    __nv_bfloat16 *p_xb, *p_wT;
    cudaGetSymbolAddress((void**)&p_fs, g_fs);
    cudaGetSymbolAddress((void**)&p_fd, g_fd);
    cudaGetSymbolAddress((void**)&p_xb, g_xb);
    cudaGetSymbolAddress((void**)&p_wT, g_wT);
    const int WSLOT = HD * HD;

    const int T = 256;
    dim3 ggrid(HD / TBN, cdiv(NN, TBM), 2);
    int gat_grid = cdiv(NN * NH * 32, T);

    // slots 1-3: conversions + init (GEMM1 does not need the CSR)
    k_cvt_in<<<cdiv(NN * FIN / 4, T), T>>>(inputs);
    k_cvt_w<<<dim3(cdiv(HD * HD, T), 1, 6), T>>>(W1s, W1d, W2s, W2d, W3s, W3d);
    k_init<<<cdiv(NN, T), T>>>();
    // slot 4 (profiled): layer-1 dual GEMM
    k_gemm<<<ggrid, 256>>>(p_xb, p_wT, p_wT + WSLOT, p_fs, p_fd, NN, FIN, HD);
    // CSR build (needed from gat1 on)
    k_hist<<<cdiv(EE, T), T>>>(dst);
    k_scan<<<1, 1024>>>();
    k_scatter<<<cdiv(EE, T), T>>>(src, dst);

    k_gat<<<gat_grid, T>>>(a1, b1);
    k_gemm<<<ggrid, 256>>>(p_xb, p_wT + 2 * WSLOT, p_wT + 3 * WSLOT, p_fs, p_fd, NN, HD, HD);
    k_gat<<<gat_grid, T>>>(a2, b2);
    k_gemm<<<ggrid, 256>>>(p_xb, p_wT + 4 * WSLOT, p_wT + 5 * WSLOT, p_fs, p_fd, NN, HD, HD);
    k_gat<<<gat_grid, T>>>(a3, b3);

    k_poolmean<<<cdiv(NN * DD, T), T>>>(gid);
    k_head<<<GG, 128>>>(p1, p2, p3, Wex, bex, Wpat, bpat,
                        Wc1, bc1, Wc2, bc2, Wc3, bc3, (float*)d_out);
}

// round 7
// speedup vs baseline: 1.4129x; 1.0171x over previous
#include <cuda_runtime.h>
#include <cuda_bf16.h>
#include <math.h>
#include <stdint.h>

// Problem constants (fixed by the reference)
#define NN   50000
#define EE   400000
#define FIN  128
#define NH   3
#define DD   64
#define HD   192   // NH*DD
#define GG   64
#define PP   64

// ---------------- scratch (device globals; no allocation) ----------------
__device__ float g_fs[(size_t)NN * HD];
__device__ float g_fd[(size_t)NN * HD];
__device__ __nv_bfloat16 g_xb[(size_t)NN * HD];   // bf16 activations (GEMM A input)
__device__ __nv_bfloat16 g_wT[6 * HD * HD];       // 6 transposed bf16 weight mats [N][K]
__device__ float g_gsum[GG * DD];
__device__ float g_gcnt[GG];
// CSR by dst (built once per launch; dst does not change across layers)
__device__ int g_deg[NN];
__device__ int g_off[NN + 1];
__device__ int g_cur[NN];
__device__ int g_esrc[EE];

static inline int cdiv(int a, int b) { return (a + b - 1) / b; }

// ---------------- conversions ----------------
__global__ void k_cvt_in(const float* __restrict__ in) {
    int idx = blockIdx.x * blockDim.x + threadIdx.x;   // float4 index
    if (idx >= NN * FIN / 4) return;
    float4 v = ((const float4*)in)[idx];
    __nv_bfloat162 lo = __floats2bfloat162_rn(v.x, v.y);
    __nv_bfloat162 hi = __floats2bfloat162_rn(v.z, v.w);
    uint32_t* o = (uint32_t*)g_xb;
    o[idx * 2 + 0] = *(uint32_t*)&lo;
    o[idx * 2 + 1] = *(uint32_t*)&hi;
}

// weights fp32 [K][N] -> g_wT bf16 [N][K], slot z (z<2: K=FIN else K=HD)
__global__ void k_cvt_w(const float* __restrict__ w0, const float* __restrict__ w1,
                        const float* __restrict__ w2, const float* __restrict__ w3,
                        const float* __restrict__ w4, const float* __restrict__ w5) {
    int z = blockIdx.z;
    const float* in = (z == 0) ? w0 : (z == 1) ? w1 : (z == 2) ? w2
                    : (z == 3) ? w3 : (z == 4) ? w4 : w5;
    int K = (z < 2) ? FIN : HD;
    int idx = blockIdx.x * blockDim.x + threadIdx.x;
    if (idx >= K * HD) return;
    int n = idx / K, k = idx - n * K;
    g_wT[(size_t)z * HD * HD + (size_t)n * K + k] = __float2bfloat16(in[(size_t)k * HD + n]);
}

// ---------------- CSR build ----------------
__global__ void k_init() {
    int idx = blockIdx.x * blockDim.x + threadIdx.x;
    if (idx < NN) g_deg[idx] = 0;
    if (idx < GG * DD) g_gsum[idx] = 0.0f;
    if (idx < GG) g_gcnt[idx] = 0.0f;
}

__global__ void k_hist(const int* __restrict__ dst) {
    int e = blockIdx.x * blockDim.x + threadIdx.x;
    if (e < EE) atomicAdd(&g_deg[dst[e]], 1);
}

// single-block exclusive scan of g_deg -> g_off (and g_cur copy)
__global__ void k_scan() {
    __shared__ int s_warp[32];
    int tid = threadIdx.x;
    int lane = tid & 31, wid = tid >> 5;
    int running = 0;
    for (int base = 0; base < NN; base += 1024) {
        int i = base + tid;
        int v = (i < NN) ? g_deg[i] : 0;
        int x = v;
#pragma unroll
        for (int o = 1; o < 32; o <<= 1) {
            int y = __shfl_up_sync(0xFFFFFFFFu, x, o);
            if (lane >= o) x += y;
        }
        if (lane == 31) s_warp[wid] = x;
        __syncthreads();
        if (wid == 0) {
            int w = s_warp[lane];
#pragma unroll
            for (int o = 1; o < 32; o <<= 1) {
                int y = __shfl_up_sync(0xFFFFFFFFu, w, o);
                if (lane >= o) w += y;
            }
            s_warp[lane] = w;
        }
        __syncthreads();
        int excl = running + x - v + (wid > 0 ? s_warp[wid - 1] : 0);
        if (i < NN) { g_off[i] = excl; g_cur[i] = excl; }
        int total = s_warp[31];
        __syncthreads();
        running += total;
    }
    if (tid == 0) g_off[NN] = running;
}

__global__ void k_scatter(const int* __restrict__ src, const int* __restrict__ dst) {
    int e = blockIdx.x * blockDim.x + threadIdx.x;
    if (e >= EE) return;
    int t = dst[e];
    int pos = atomicAdd(&g_cur[t], 1);
    g_esrc[pos] = src[e];
}

// ---------------- bf16 tensor-core dual GEMM (unchanged from R5) ----------------
#define TBM 128
#define TBN 64
#define TBK 32
#define ASTR 20
#define BSTR 20
__global__ void k_gemm(const __nv_bfloat16* __restrict__ A,
                       const __nv_bfloat16* __restrict__ BT0,
                       const __nv_bfloat16* __restrict__ BT1,
                       float* __restrict__ C0, float* __restrict__ C1,
                       int M, int K, int Nc) {
    __shared__ uint32_t As[TBM * ASTR];
    __shared__ uint32_t Bs[TBN * BSTR];
    const __nv_bfloat16* BT = blockIdx.z ? BT1 : BT0;
    float* C = blockIdx.z ? C1 : C0;

    int tid = threadIdx.x;
    int warp = tid >> 5, lane = tid & 31;
    int warp_m = warp & 3, warp_n = warp >> 2;
    int row0 = blockIdx.y * TBM;
    int col0 = blockIdx.x * TBN;
    int gid = lane >> 2, tig = lane & 3;

    float acc[2][4][4] = {};

    for (int k0 = 0; k0 < K; k0 += TBK) {
#pragma unroll
        for (int j = 0; j < 2; j++) {
            int c = tid + j * 256;
            int r = c >> 2, q = c & 3;
            uint4 v = make_uint4(0, 0, 0, 0);
            if (row0 + r < M)
                v = *(const uint4*)(A + (size_t)(row0 + r) * K + k0 + q * 8);
            *(uint4*)&As[r * ASTR + q * 4] = v;
        }
        {
            int n = tid >> 2, q = tid & 3;
            uint4 v = *(const uint4*)(BT + (size_t)(col0 + n) * K + k0 + q * 8);
            *(uint4*)&Bs[n * BSTR + q * 4] = v;
        }
        __syncthreads();

#pragma unroll
        for (int ks = 0; ks < 2; ks++) {
            int off = ks * 8;
            uint32_t a[2][4], b[4][2];
#pragma unroll
            for (int mt = 0; mt < 2; mt++) {
                int r = warp_m * 32 + mt * 16 + gid;
                int base = r * ASTR + off + tig;
                a[mt][0] = As[base];
                a[mt][1] = As[base + 8 * ASTR];
                a[mt][2] = As[base + 4];
                a[mt][3] = As[base + 8 * ASTR + 4];
            }
#pragma unroll
            for (int nt = 0; nt < 4; nt++) {
                int n = warp_n * 32 + nt * 8 + gid;
                b[nt][0] = Bs[n * BSTR + off + tig];
                b[nt][1] = Bs[n * BSTR + off + tig + 4];
            }
#pragma unroll
            for (int mt = 0; mt < 2; mt++)
#pragma unroll
                for (int nt = 0; nt < 4; nt++)
                    asm volatile(
                        "mma.sync.aligned.m16n8k16.row.col.f32.bf16.bf16.f32 "
                        "{%0,%1,%2,%3}, {%4,%5,%6,%7}, {%8,%9}, {%0,%1,%2,%3};"
                        : "+f"(acc[mt][nt][0]), "+f"(acc[mt][nt][1]),
                          "+f"(acc[mt][nt][2]), "+f"(acc[mt][nt][3])
                        : "r"(a[mt][0]), "r"(a[mt][1]), "r"(a[mt][2]), "r"(a[mt][3]),
                          "r"(b[nt][0]), "r"(b[nt][1]));
        }
        __syncthreads();
    }

#pragma unroll
    for (int mt = 0; mt < 2; mt++) {
        int r = row0 + warp_m * 32 + mt * 16 + gid;
#pragma unroll
        for (int nt = 0; nt < 4; nt++) {
            int cn = col0 + warp_n * 32 + nt * 8 + tig * 2;
            if (r < M)
                *(float2*)(C + (size_t)r * Nc + cn) = make_float2(acc[mt][nt][0], acc[mt][nt][1]);
            if (r + 8 < M)
                *(float2*)(C + (size_t)(r + 8) * Nc + cn) = make_float2(acc[mt][nt][2], acc[mt][nt][3]);
        }
    }
}

// ---------------- fused GATv2 edge softmax + aggregation (unroll-2) ----------
// One warp per (dst node, head). TWO independent online-softmax states over
// alternating edges; merged at the end. Halves the dependent chain per edge.
__global__ void k_gat(const float* __restrict__ attn, const float* __restrict__ bias) {
    int w = (blockIdx.x * blockDim.x + threadIdx.x) >> 5;
    int lane = threadIdx.x & 31;
    if (w >= NN * NH) return;
    int n = w / NH, h = w - n * NH;
    int base = h * DD + lane * 2;

    float2 fd2 = *(const float2*)(g_fd + (size_t)n * HD + base);
    float2 a2  = __ldg((const float2*)(attn + base));

    float mA = -INFINITY, dA = 0.f, xA = 0.f, yA = 0.f;
    float mB = -INFINITY, dB = 0.f, xB = 0.f, yB = 0.f;

    int beg = g_off[n], end = g_off[n + 1];
    int i = beg;
    for (; i + 2 <= end; i += 2) {
        int s0 = __ldg(&g_esrc[i]);
        int s1 = __ldg(&g_esrc[i + 1]);
        float2 f0 = *(const float2*)(g_fs + (size_t)s0 * HD + base);
        float2 f1 = *(const float2*)(g_fs + (size_t)s1 * HD + base);

        float v0x = f0.x + fd2.x; v0x = v0x > 0.f ? v0x : 0.2f * v0x;
        float v1x = f1.x + fd2.x; v1x = v1x > 0.f ? v1x : 0.2f * v1x;
        float v0y = f0.y + fd2.y; v0y = v0y > 0.f ? v0y : 0.2f * v0y;
        float v1y = f1.y + fd2.y; v1y = v1y > 0.f ? v1y : 0.2f * v1y;
        float p0 = fmaf(a2.y, v0y, a2.x * v0x);
        float p1 = fmaf(a2.y, v1y, a2.x * v1x);
#pragma unroll
        for (int o = 16; o; o >>= 1) {
            p0 += __shfl_xor_sync(0xFFFFFFFFu, p0, o);
            p1 += __shfl_xor_sync(0xFFFFFFFFu, p1, o);
        }
        if (p0 <= mA) { float e = expf(p0 - mA); dA += e; xA = fmaf(e, f0.x, xA); yA = fmaf(e, f0.y, yA); }
        else { float sc = expf(mA - p0); dA = fmaf(dA, sc, 1.f); xA = fmaf(xA, sc, f0.x); yA = fmaf(yA, sc, f0.y); mA = p0; }
        if (p1 <= mB) { float e = expf(p1 - mB); dB += e; xB = fmaf(e, f1.x, xB); yB = fmaf(e, f1.y, yB); }
        else { float sc = expf(mB - p1); dB = fmaf(dB, sc, 1.f); xB = fmaf(xB, sc, f1.x); yB = fmaf(yB, sc, f1.y); mB = p1; }
    }
    if (i < end) {   // tail edge -> state A
        int s0 = __ldg(&g_esrc[i]);
        float2 f0 = *(const float2*)(g_fs + (size_t)s0 * HD + base);
        float vx = f0.x + fd2.x; vx = vx > 0.f ? vx : 0.2f * vx;
        float vy = f0.y + fd2.y; vy = vy > 0.f ? vy : 0.2f * vy;
        float p = fmaf(a2.y, vy, a2.x * vx);
#pragma unroll
        for (int o = 16; o; o >>= 1) p += __shfl_xor_sync(0xFFFFFFFFu, p, o);
        if (p <= mA) { float e = expf(p - mA); dA += e; xA = fmaf(e, f0.x, xA); yA = fmaf(e, f0.y, yA); }
        else { float sc = expf(mA - p); dA = fmaf(dA, sc, 1.f); xA = fmaf(xA, sc, f0.x); yA = fmaf(yA, sc, f0.y); mA = p; }
    }
    // merge state B into A
    if (mB != -INFINITY) {
        if (mB <= mA) {
            float sc = expf(mB - mA);
            dA = fmaf(dB, sc, dA); xA = fmaf(xB, sc, xA); yA = fmaf(yB, sc, yA);
        } else {
            float sc = expf(mA - mB);
            dA = fmaf(dA, sc, dB); xA = fmaf(xA, sc, xB); yA = fmaf(yA, sc, yB);
        }
    }

    float inv = 1.f / fmaxf(dA, 1e-9f);
    float2 b2 = __ldg((const float2*)(bias + base));
    float ox = fmaf(xA, inv, b2.x);
    float oy = fmaf(yA, inv, b2.y);
    __nv_bfloat162 pk = __floats2bfloat162_rn(ox, oy);
    ((uint32_t*)g_xb)[(size_t)n * (HD / 2) + h * (DD / 2) + lane] = *(uint32_t*)&pk;
}

// layer-3: mean over heads (bf16 h) + graph pooling
__global__ void k_poolmean(const int* __restrict__ gid) {
    int idx = blockIdx.x * blockDim.x + threadIdx.x;
    if (idx >= NN * DD) return;
    int n = idx / DD, d = idx - n * DD;
    const __nv_bfloat16* p = g_xb + (size_t)n * HD;
    float v = (__bfloat162float(p[d]) + __bfloat162float(p[DD + d]) +
               __bfloat162float(p[2 * DD + d])) * (1.0f / 3.0f);
    int g = __ldg(&gid[n]);
    atomicAdd(&g_gsum[g * DD + d], v);
    if (d == 0) atomicAdd(&g_gcnt[g], 1.0f);
}

// ---------------- pattern branch + classifier head ----------------
__global__ void k_head(const float* __restrict__ p1, const float* __restrict__ p2,
                       const float* __restrict__ p3,
                       const float* __restrict__ Wex, const float* __restrict__ bex,
                       const float* __restrict__ Wpat, const float* __restrict__ bpat,
                       const float* __restrict__ Wc1, const float* __restrict__ bc1,
                       const float* __restrict__ Wc2, const float* __restrict__ bc2,
                       const float* __restrict__ Wc3, const float* __restrict__ bc3,
                       float* __restrict__ out) {
    int g = blockIdx.x;
    int tid = threadIdx.x;
    __shared__ float s_ex[96];
    __shared__ float s_x[128];
    __shared__ float s_c1[64];
    __shared__ float s_c2[32];

    if (tid < 96) {
        int part = tid / 32, j = tid % 32;
        const float* p = (part == 0) ? p1 : (part == 1) ? p2 : p3;
        float acc = bex[j];
        for (int k = 0; k < PP; k++) acc = fmaf(p[g * PP + k], Wex[k * 32 + j], acc);
        s_ex[tid] = acc;
    }
    __syncthreads();

    if (tid < 64) {
        float cnt = fmaxf(g_gcnt[g], 1.0f);
        s_x[tid] = g_gsum[g * DD + tid] / cnt;
    } else {
        int j = tid - 64;
        float acc = bpat[j];
        for (int k = 0; k < 96; k++) acc = fmaf(s_ex[k], Wpat[k * PP + j], acc);
        s_x[tid] = acc > 0.f ? acc : 0.01f * acc;
    }
    __syncthreads();

    if (tid < 64) {
        float acc = bc1[tid];
        for (int k = 0; k < 128; k++) acc = fmaf(s_x[k], Wc1[k * 64 + tid], acc);
        s_c1[tid] = acc > 0.f ? acc : 0.01f * acc;
    }
    __syncthreads();

    if (tid < 32) {
        float acc = bc2[tid];
        for (int k = 0; k < 64; k++) acc = fmaf(s_c1[k], Wc2[k * 32 + tid], acc);
        s_c2[tid] = acc > 0.f ? acc : 0.01f * acc;
    }
    __syncthreads();

    if (tid < 2) {
        float acc = bc3[tid];
        for (int k = 0; k < 32; k++) acc = fmaf(s_c2[k], Wc3[k * 2 + tid], acc);
        out[g * 2 + tid] = acc;
    }
}

// ---------------- driver ----------------
extern "C" void kernel_launch(void* const* d_in, const int* in_sizes, int n_in,
                              void* d_out, int out_size) {
    const float* inputs = (const float*)d_in[0];
    const int*   src    = (const int*)d_in[1];
    const int*   dst    = (const int*)d_in[2];
    const int*   gid    = (const int*)d_in[3];
    const float* p1     = (const float*)d_in[4];
    const float* p2     = (const float*)d_in[5];
    const float* p3     = (const float*)d_in[6];
    const float* W1s = (const float*)d_in[7],  *W1d = (const float*)d_in[8];
    const float* a1  = (const float*)d_in[9],  *b1  = (const float*)d_in[10];
    const float* W2s = (const float*)d_in[11], *W2d = (const float*)d_in[12];
    const float* a2  = (const float*)d_in[13], *b2  = (const float*)d_in[14];
    const float* W3s = (const float*)d_in[15], *W3d = (const float*)d_in[16];
    const float* a3  = (const float*)d_in[17], *b3  = (const float*)d_in[18];
    const float* Wex = (const float*)d_in[19], *bex = (const float*)d_in[20];
    const float* Wpat= (const float*)d_in[21], *bpat= (const float*)d_in[22];
    const float* Wc1 = (const float*)d_in[23], *bc1 = (const float*)d_in[24];
    const float* Wc2 = (const float*)d_in[25], *bc2 = (const float*)d_in[26];
    const float* Wc3 = (const float*)d_in[27], *bc3 = (const float*)d_in[28];

    float *p_fs, *p_fd;
    __nv_bfloat16 *p_xb, *p_wT;
    cudaGetSymbolAddress((void**)&p_fs, g_fs);
    cudaGetSymbolAddress((void**)&p_fd, g_fd);
    cudaGetSymbolAddress((void**)&p_xb, g_xb);
    cudaGetSymbolAddress((void**)&p_wT, g_wT);
    const int WSLOT = HD * HD;

    // one-time stream/event creation (host resources only; no device memory)
    static cudaStream_t s2 = nullptr;
    static cudaEvent_t evFork = nullptr, evJoin = nullptr;
    if (!s2) {
        cudaStreamCreateWithFlags(&s2, cudaStreamNonBlocking);
        cudaEventCreateWithFlags(&evFork, cudaEventDisableTiming);
        cudaEventCreateWithFlags(&evJoin, cudaEventDisableTiming);
    }

    const int T = 256;
    dim3 ggrid(HD / TBN, cdiv(NN, TBM), 2);
    int gat_grid = cdiv(NN * NH * 32, T);

    // fork: CSR build on s2, concurrent with cvt + GEMM1 on the main stream
    cudaEventRecord(evFork, 0);
    cudaStreamWaitEvent(s2, evFork, 0);
    k_init<<<cdiv(NN, T), T, 0, s2>>>();
    k_hist<<<cdiv(EE, T), T, 0, s2>>>(dst);
    k_scan<<<1, 1024, 0, s2>>>();
    k_scatter<<<cdiv(EE, T), T, 0, s2>>>(src, dst);
    cudaEventRecord(evJoin, s2);

    k_cvt_in<<<cdiv(NN * FIN / 4, T), T>>>(inputs);
    k_cvt_w<<<dim3(cdiv(HD * HD, T), 1, 6), T>>>(W1s, W1d, W2s, W2d, W3s, W3d);
    k_gemm<<<ggrid, 256>>>(p_xb, p_wT, p_wT + WSLOT, p_fs, p_fd, NN, FIN, HD);

    // join: gat needs the CSR
    cudaStreamWaitEvent(0, evJoin, 0);

    k_gat<<<gat_grid, T>>>(a1, b1);
    k_gemm<<<ggrid, 256>>>(p_xb, p_wT + 2 * WSLOT, p_wT + 3 * WSLOT, p_fs, p_fd, NN, HD, HD);
    k_gat<<<gat_grid, T>>>(a2, b2);
    k_gemm<<<ggrid, 256>>>(p_xb, p_wT + 4 * WSLOT, p_wT + 5 * WSLOT, p_fs, p_fd, NN, HD, HD);
    k_gat<<<gat_grid, T>>>(a3, b3);

    k_poolmean<<<cdiv(NN * DD, T), T>>>(gid);
    k_head<<<GG, 128>>>(p1, p2, p3, Wex, bex, Wpat, bpat,
                        Wc1, bc1, Wc2, bc2, Wc3, bc3, (float*)d_out);
}